// round 10
// baseline (speedup 1.0000x reference)
#include <cuda_runtime.h>
#include <cuda_bf16.h>
#include <math.h>

// GAT layer, algebraically folded + fissioned:
//  K1 prep : Wt/Wn folds, cb, + bf16-packed Wn for phase-2
//  K2 eb   : eb[b] = Wt @ x_t[b] + cb                     (65536 x 16)
//  K3 main : e_n = leaky(attn2 @ relu(Wn x_n + eb) + b2); a = softmax(e);
//            s[b] = sum_n a_n x_n                          (65536 x 64)
//            -- phase-2 operands staged in bf16 (half crossbar bytes),
//               math in fp32 via fma.rn.f32x2; phase-4 uses fp32 tile.
//  K4 out  : out = elu(align_w @ s + align_b)   [smem-tiled GEMM, f32x2]

#define GRID 1184
typedef unsigned long long ull;

__device__ float    WtP_g[1024];
__device__ float    CBP_g[16];
__device__ unsigned WnB_g[512];        // bf16x2-packed folded Wn, [p4][hI][blk][slot]
__device__ float    eb_g[65536 * 16];  // 4 MB scratch
__device__ float    s_g[65536 * 64];   // 16 MB scratch

__device__ __forceinline__ ull splat2(float a) {
    ull r; asm("mov.b64 %0, {%1, %1};" : "=l"(r) : "f"(a)); return r;
}
__device__ __forceinline__ ull pack2u(unsigned lo, unsigned hi) {
    ull r; asm("mov.b64 %0, {%1, %2};" : "=l"(r) : "r"(lo), "r"(hi)); return r;
}
__device__ __forceinline__ ull bfpair(unsigned w) {          // (bf_lo, bf_hi) -> (f32, f32)
    return pack2u(w << 16, w & 0xFFFF0000u);
}
__device__ __forceinline__ ull bfsplat_lo(unsigned w) {
    unsigned v = w << 16; return pack2u(v, v);
}
__device__ __forceinline__ ull bfsplat_hi(unsigned w) {
    unsigned v = w & 0xFFFF0000u; return pack2u(v, v);
}
__device__ __forceinline__ void fma2(ull& acc, ull a, ull b) {
    asm("fma.rn.f32x2 %0, %1, %2, %0;" : "+l"(acc) : "l"(a), "l"(b));
}
__device__ __forceinline__ float2 unpack2(ull v) {
    float2 r; asm("mov.b64 {%0, %1}, %2;" : "=f"(r.x), "=f"(r.y) : "l"(v)); return r;
}

// ---------------- K1: fold weights ----------------
__global__ void prep_kernel(const float* __restrict__ align_w,
                            const float* __restrict__ align_b,
                            const float* __restrict__ a1w,
                            const float* __restrict__ a1b) {
    int idx = blockIdx.x * blockDim.x + threadIdx.x;
    if (idx < 1024) {
        int c = idx >> 4, h = idx & 15;
        float st = 0.f;
        for (int d = 0; d < 64; d++)
            st = fmaf(a1w[h * 128 + d], align_w[d * 64 + c], st);
        WtP_g[c * 16 + h] = st;
    } else if (idx < 1040) {
        int h = idx - 1024;
        float s = 0.f;
        for (int d = 0; d < 64; d++)
            s += (a1w[h * 128 + d] + a1w[h * 128 + 64 + d]) * align_b[d];
        CBP_g[h] = s + a1b[h];
    } else if (idx >= 1536 && idx < 2048) {
        // bf16-packed Wn word: (p4, hI, cc, hp) -> bf16x2(Wn[c][h0], Wn[c][h1])
        int w  = idx - 1536;
        int p4 = w >> 5, r = w & 31;
        int hI = (r >> 3) & 3, cc = (r >> 1) & 3, hp = r & 1;
        int c  = 4 * p4 + cc;
        int h0 = 4 * hI + 2 * hp;
        float s0 = 0.f, s1 = 0.f;
        for (int d = 0; d < 64; d++) {
            float aw = align_w[d * 64 + c];
            s0 = fmaf(a1w[h0 * 128 + 64 + d],       aw, s0);
            s1 = fmaf(a1w[(h0 + 1) * 128 + 64 + d], aw, s1);
        }
        __nv_bfloat162 bw = __float22bfloat162_rn(make_float2(s0, s1));
        int word = ((p4 * 4 + hI) * 2 + (cc >> 1)) * 4 + (cc & 1) * 2 + hp;
        WnB_g[word] = *(unsigned*)&bw;
    }
}

// ---------------- K2: eb[b] = Wt @ x_t[b] + cb ----------------
__global__ __launch_bounds__(128) void eb_kernel(const float* __restrict__ xt) {
    __shared__ float xs[512];
    __shared__ float wt[1024];
    __shared__ float cbs[16];
    const int tid = threadIdx.x;
    for (int i = tid; i < 1024; i += 128) wt[i] = WtP_g[i];
    if (tid < 16) cbs[tid] = CBP_g[tid];
    const int b0 = blockIdx.x * 8;
    for (int i = tid; i < 512; i += 128) xs[i] = xt[(size_t)b0 * 64 + i];
    __syncthreads();
    const int bl = tid >> 4, h = tid & 15;
    float acc = 0.f;
#pragma unroll 8
    for (int c = 0; c < 64; c++) acc = fmaf(xs[bl * 64 + c], wt[c * 16 + h], acc);
    eb_g[(size_t)(b0 + bl) * 16 + h] = acc + cbs[h];
}

// ---------------- K3: main (attention + weighted sum) ----------------
// dynamic smem layout (57920 B):
//   [0      ) float4 xs4[4][576]   fp32 x tile, swizzled        36864
//   [36864  ) ull    xb8[4][576]   bf16 x tile, swizzled        18432
//   [55296  ) uint4  wnb[128]      bf16 Wn packed                2048
//   [57344  ) float  a_s[4][36]    attention weights              576
__global__ __launch_bounds__(128, 4)
void gat_kernel(const float* __restrict__ xn,
                const float* __restrict__ a2w,
                const float* __restrict__ a2b) {
    extern __shared__ char sm[];
    float4* xs4a = (float4*)sm;
    ull*    xb8a = (ull*)(sm + 36864);
    uint4*  wnb  = (uint4*)(sm + 55296);
    float*  a_sa = (float*)(sm + 57344);

    const int tid  = threadIdx.x;
    const int wid  = tid >> 5;
    const int lane = tid & 31;
    const int nI   = lane & 7;
    const int hI   = lane >> 3;
    const int cq   = lane & 15;
    const int rh   = lane >> 4;

    float4* xw4 = xs4a + wid * 576;
    ull*    xbw = xb8a + wid * 576;
    float*  a_s = a_sa + wid * 36;

    if (tid < 128) wnb[tid] = ((const uint4*)WnB_g)[tid];
    if (lane < 16) {                                   // zero pad row 35
        xw4[560 + lane] = make_float4(0.f, 0.f, 0.f, 0.f);
        xbw[560 + lane] = 0ull;
    }

    float4 a2v = __ldg((const float4*)a2w + hI);
    const float a2r0 = a2v.x, a2r1 = a2v.y, a2r2 = a2v.z, a2r3 = a2v.w;
    const float b2 = __ldg(a2b);

    __syncthreads();

    for (int g = blockIdx.x; g < 16384; g += GRID) {
        const int b = g * 4 + wid;

        // ---- phase 1: stage x_neigh fp32 (swizzled) + bf16 copy
        {
            const float4* src4 = (const float4*)xn + (size_t)b * 560;
#pragma unroll
            for (int k = 0; k < 18; k++) {
                int idx = k * 32 + lane;
                if (idx < 560) {
                    int row = idx >> 4, c4 = idx & 15;
                    float4 v = src4[idx];
                    xw4[row * 16 + (c4 ^ (row & 7))] = v;
                    __nv_bfloat162 b01 = __float22bfloat162_rn(make_float2(v.x, v.y));
                    __nv_bfloat162 b23 = __float22bfloat162_rn(make_float2(v.z, v.w));
                    xbw[row * 16 + (c4 ^ ((row & 7) << 1))] =
                        pack2u(*(unsigned*)&b01, *(unsigned*)&b23);
                }
            }
        }
        __syncwarp();

        // ---- phase 2: u[j][h-pairs] = (Wn @ x_row)[4hI..], bf16 operands, f32 math
        ull u2[5][2];
#pragma unroll
        for (int j = 0; j < 5; j++) { u2[j][0] = 0ull; u2[j][1] = 0ull; }
        const bool has2 = (nI < 3);
        const int row4 = has2 ? (nI + 32) : 35;

#pragma unroll 4
        for (int p4 = 0; p4 < 16; p4++) {
            uint4 B0 = wnb[(p4 * 4 + hI) * 2 + 0];
            uint4 B1 = wnb[(p4 * 4 + hI) * 2 + 1];
            ull w00 = bfpair(B0.x), w01 = bfpair(B0.y);   // cc0: (h0,h1),(h2,h3)
            ull w10 = bfpair(B0.z), w11 = bfpair(B0.w);   // cc1
            ull w20 = bfpair(B1.x), w21 = bfpair(B1.y);   // cc2
            ull w30 = bfpair(B1.z), w31 = bfpair(B1.w);   // cc3
#pragma unroll
            for (int j = 0; j < 5; j++) {
                int row = (j < 4) ? (nI + 8 * j) : row4;
                uint2 xw = *(const uint2*)&xbw[row * 16 + (p4 ^ ((row & 7) << 1))];
                ull a0 = bfsplat_lo(xw.x), a1 = bfsplat_hi(xw.x);
                ull a2 = bfsplat_lo(xw.y), a3 = bfsplat_hi(xw.y);
                fma2(u2[j][0], a0, w00); fma2(u2[j][1], a0, w01);
                fma2(u2[j][0], a1, w10); fma2(u2[j][1], a1, w11);
                fma2(u2[j][0], a2, w20); fma2(u2[j][1], a2, w21);
                fma2(u2[j][0], a3, w30); fma2(u2[j][1], a3, w31);
            }
        }

        // ---- eb (precomputed target contribution incl. bias)
        float4 ebv = __ldg((const float4*)eb_g + (size_t)b * 4 + hI);

        // ---- phase 3: e, leaky relu, softmax over n
        float e[5];
#pragma unroll
        for (int j = 0; j < 5; j++) {
            float2 lo = unpack2(u2[j][0]), hi = unpack2(u2[j][1]);
            float pe;
            pe =      a2r0 * fmaxf(lo.x + ebv.x, 0.f);
            pe = fmaf(a2r1,  fmaxf(lo.y + ebv.y, 0.f), pe);
            pe = fmaf(a2r2,  fmaxf(hi.x + ebv.z, 0.f), pe);
            pe = fmaf(a2r3,  fmaxf(hi.y + ebv.w, 0.f), pe);
            pe += __shfl_xor_sync(0xffffffffu, pe, 8);
            pe += __shfl_xor_sync(0xffffffffu, pe, 16);
            float ev = pe + b2;
            e[j] = ev > 0.f ? ev : 0.2f * ev;
        }
        if (!has2) e[4] = -INFINITY;

        float mx = e[0];
#pragma unroll
        for (int j = 1; j < 5; j++) mx = fmaxf(mx, e[j]);
#pragma unroll
        for (int m = 1; m <= 4; m <<= 1) mx = fmaxf(mx, __shfl_xor_sync(0xffffffffu, mx, m));

        float ax[5]; float sum = 0.f;
#pragma unroll
        for (int j = 0; j < 5; j++) { ax[j] = __expf(e[j] - mx); sum += ax[j]; }
#pragma unroll
        for (int m = 1; m <= 4; m <<= 1) sum += __shfl_xor_sync(0xffffffffu, sum, m);
        float rinv = 1.0f / sum;

        if (hI == 0) {
#pragma unroll
            for (int j = 0; j < 4; j++) a_s[nI + 8 * j] = ax[j] * rinv;
            if (has2) a_s[nI + 32] = ax[4] * rinv;
            if (nI == 3) a_s[35] = 0.f;   // pad row weight
        }
        __syncwarp();

        // ---- phase 4: s[c] = sum_n a_n x_n[c]; fp32 tile; lane=(cq,rh)
        float2 ap[9];
#pragma unroll
        for (int i = 0; i < 9; i++) ap[i] = *(const float2*)&a_s[rh * 18 + 2 * i];

        float4 acc = make_float4(0.f, 0.f, 0.f, 0.f);
#pragma unroll
        for (int q = 0; q < 18; q++) {
            int row = rh * 18 + q;                 // row 35 contributes 0 (a=0, x=0)
            float a = (q & 1) ? ap[q >> 1].y : ap[q >> 1].x;
            float4 xv = xw4[row * 16 + (cq ^ (row & 7))];
            acc.x = fmaf(a, xv.x, acc.x);
            acc.y = fmaf(a, xv.y, acc.y);
            acc.z = fmaf(a, xv.z, acc.z);
            acc.w = fmaf(a, xv.w, acc.w);
        }
        acc.x += __shfl_xor_sync(0xffffffffu, acc.x, 16);
        acc.y += __shfl_xor_sync(0xffffffffu, acc.y, 16);
        acc.z += __shfl_xor_sync(0xffffffffu, acc.z, 16);
        acc.w += __shfl_xor_sync(0xffffffffu, acc.w, 16);
        if (rh == 0)
            *((float4*)(s_g + (size_t)b * 64) + cq) = acc;
        __syncwarp();
    }
}

// ---------------- K4: out = elu(align_w @ s + align_b) ----------------
#define OPITCH 68
__global__ __launch_bounds__(256)
void out_kernel(const float* __restrict__ aw,
                const float* __restrict__ abv,
                float* __restrict__ out) {
    __shared__ __align__(16) float s_s[64 * OPITCH];
    __shared__ __align__(16) float w_t[64 * OPITCH];
    __shared__ float ab_s[64];

    const int tid = threadIdx.x;
    const int b0  = blockIdx.x * 64;

#pragma unroll
    for (int k = 0; k < 16; k++) {
        int idx = k * 256 + tid;
        int d = idx >> 6, c = idx & 63;
        w_t[c * OPITCH + d] = aw[idx];
    }
    if (tid < 64) ab_s[tid] = abv[tid];

#pragma unroll
    for (int k = 0; k < 4; k++) {
        int idx4 = k * 256 + tid;
        int bl = idx4 >> 4, c4 = idx4 & 15;
        *(float4*)&s_s[bl * OPITCH + c4 * 4] =
            ((const float4*)(s_g + (size_t)(b0 + bl) * 64))[c4];
    }
    __syncthreads();

    const int tx = tid & 15;
    const int ty = tid >> 4;

    ull acc2[4][2];
#pragma unroll
    for (int bi = 0; bi < 4; bi++) { acc2[bi][0] = 0ull; acc2[bi][1] = 0ull; }

#pragma unroll
    for (int cs = 0; cs < 16; cs++) {
        ull wv[4][2];
#pragma unroll
        for (int j = 0; j < 4; j++) {
            const float* wp = &w_t[(4 * cs + j) * OPITCH + 4 * tx];
            wv[j][0] = *(const ull*)&wp[0];
            wv[j][1] = *(const ull*)&wp[2];
        }
#pragma unroll
        for (int bi = 0; bi < 4; bi++) {
            float4 sv = *(const float4*)&s_s[(4 * ty + bi) * OPITCH + 4 * cs];
            ull a0 = splat2(sv.x), a1 = splat2(sv.y);
            ull a2 = splat2(sv.z), a3 = splat2(sv.w);
            fma2(acc2[bi][0], a0, wv[0][0]); fma2(acc2[bi][1], a0, wv[0][1]);
            fma2(acc2[bi][0], a1, wv[1][0]); fma2(acc2[bi][1], a1, wv[1][1]);
            fma2(acc2[bi][0], a2, wv[2][0]); fma2(acc2[bi][1], a2, wv[2][1]);
            fma2(acc2[bi][0], a3, wv[3][0]); fma2(acc2[bi][1], a3, wv[3][1]);
        }
    }

    float4 abv4 = *(const float4*)&ab_s[4 * tx];
#pragma unroll
    for (int bi = 0; bi < 4; bi++) {
        float2 lo = unpack2(acc2[bi][0]), hi = unpack2(acc2[bi][1]);
        float4 o;
        o.x = lo.x + abv4.x; o.x = (o.x > 0.f) ? o.x : expm1f(o.x);
        o.y = lo.y + abv4.y; o.y = (o.y > 0.f) ? o.y : expm1f(o.y);
        o.z = hi.x + abv4.z; o.z = (o.z > 0.f) ? o.z : expm1f(o.z);
        o.w = hi.y + abv4.w; o.w = (o.w > 0.f) ? o.w : expm1f(o.w);
        *(float4*)&out[(size_t)(b0 + 4 * ty + bi) * 64 + 4 * tx] = o;
    }
}

extern "C" void kernel_launch(void* const* d_in, const int* in_sizes, int n_in,
                              void* d_out, int out_size) {
    const float* x_target = (const float*)d_in[0];
    const float* x_neigh  = (const float*)d_in[1];
    const float* align_w  = (const float*)d_in[2];
    const float* align_b  = (const float*)d_in[3];
    const float* attn1_w  = (const float*)d_in[4];
    const float* attn1_b  = (const float*)d_in[5];
    const float* attn2_w  = (const float*)d_in[6];
    const float* attn2_b  = (const float*)d_in[7];
    float* out = (float*)d_out;

    static bool attr_set = false;
    if (!attr_set) {
        cudaFuncSetAttribute(gat_kernel, cudaFuncAttributeMaxDynamicSharedMemorySize, 57920);
        attr_set = true;
    }

    prep_kernel<<<16, 128>>>(align_w, align_b, attn1_w, attn1_b);
    eb_kernel<<<8192, 128>>>(x_target);
    gat_kernel<<<GRID, 128, 57920>>>(x_neigh, attn2_w, attn2_b);
    out_kernel<<<1024, 256>>>(align_w, align_b, out);
}

// round 13
// speedup vs baseline: 1.1764x; 1.1764x over previous
#include <cuda_runtime.h>
#include <math.h>

// GAT layer, algebraically folded + fissioned:
//  K1 prep : Wn = attn1_w[:,64:]@align_w, Wt = attn1_w[:,:64]@align_w,
//            cb = (attn1_w[:,:64]+attn1_w[:,64:])@align_b + attn1_b
//  K2 eb   : eb[b] = Wt @ x_t[b] + cb                     (65536 x 16)
//  K3 main : e_n = leaky(attn2 @ relu(Wn x_n + eb) + b2); a = softmax(e);
//            s[b] = sum_n a_n x_n                          (65536 x 64)
//            -- 2-stage cp.async ping-pong: prefetch tile g+GRID while
//               computing tile g; DRAM latency fully overlapped.
//  K4 out  : out = elu(align_w @ s + align_b)   [smem-tiled GEMM, f32x2]

#define GRID 296
typedef unsigned long long ull;

__device__ float WnP_g[1024];
__device__ float WtP_g[1024];
__device__ float CBP_g[16];
__device__ float eb_g[65536 * 16];     // 4 MB scratch
__device__ float s_g[65536 * 64];      // 16 MB scratch

__device__ __forceinline__ ull splat2(float a) {
    ull r; asm("mov.b64 %0, {%1, %1};" : "=l"(r) : "f"(a)); return r;
}
__device__ __forceinline__ void fma2(ull& acc, ull a, ull b) {
    asm("fma.rn.f32x2 %0, %1, %2, %0;" : "+l"(acc) : "l"(a), "l"(b));
}
__device__ __forceinline__ float2 unpack2(ull v) {
    float2 r; asm("mov.b64 {%0, %1}, %2;" : "=f"(r.x), "=f"(r.y) : "l"(v)); return r;
}
__device__ __forceinline__ void lds_v2u64(ull& a, ull& b, unsigned addr) {
    asm volatile("ld.shared.v2.b64 {%0, %1}, [%2];" : "=l"(a), "=l"(b) : "r"(addr));
}
__device__ __forceinline__ void cp16(unsigned dst, const void* src) {
    asm volatile("cp.async.cg.shared.global [%0], [%1], 16;" :: "r"(dst), "l"(src));
}
__device__ __forceinline__ void cp_commit() {
    asm volatile("cp.async.commit_group;");
}
__device__ __forceinline__ void cp_wait1() {
    asm volatile("cp.async.wait_group 1;");
}

// ---------------- K1: fold weights ----------------
__global__ void prep_kernel(const float* __restrict__ align_w,
                            const float* __restrict__ align_b,
                            const float* __restrict__ a1w,
                            const float* __restrict__ a1b) {
    int idx = blockIdx.x * blockDim.x + threadIdx.x;
    if (idx < 1024) {
        int c = idx >> 4, h = idx & 15;
        float st = 0.f, sn = 0.f;
        for (int d = 0; d < 64; d++) {
            float aw = align_w[d * 64 + c];
            st = fmaf(a1w[h * 128 + d],      aw, st);
            sn = fmaf(a1w[h * 128 + 64 + d], aw, sn);
        }
        WtP_g[c * 16 + h] = st;
        WnP_g[c * 16 + h] = sn;
    } else if (idx < 1040) {
        int h = idx - 1024;
        float s = 0.f;
        for (int d = 0; d < 64; d++)
            s += (a1w[h * 128 + d] + a1w[h * 128 + 64 + d]) * align_b[d];
        CBP_g[h] = s + a1b[h];
    }
}

// ---------------- K2: eb[b] = Wt @ x_t[b] + cb ----------------
__global__ __launch_bounds__(128) void eb_kernel(const float* __restrict__ xt) {
    __shared__ float xs[512];
    __shared__ float wt[1024];
    __shared__ float cbs[16];
    const int tid = threadIdx.x;
    for (int i = tid; i < 1024; i += 128) wt[i] = WtP_g[i];
    if (tid < 16) cbs[tid] = CBP_g[tid];
    const int b0 = blockIdx.x * 8;
    for (int i = tid; i < 512; i += 128) xs[i] = xt[(size_t)b0 * 64 + i];
    __syncthreads();
    const int bl = tid >> 4, h = tid & 15;
    float acc = 0.f;
#pragma unroll 8
    for (int c = 0; c < 64; c++) acc = fmaf(xs[bl * 64 + c], wt[c * 16 + h], acc);
    eb_g[(size_t)(b0 + bl) * 16 + h] = acc + cbs[h];
}

// ---------------- K3: main (attention + weighted sum) ----------------
// dynamic smem (78400 B):
//   [0     ) float4 xs4[4 warps][2 stages][576]   73728  (x tiles, swizzled)
//   [73728 ) float  Wn_s[1024]                     4096
//   [77824 ) float  a_s[4][36]                      576
__global__ __launch_bounds__(128, 2)
void gat_kernel(const float* __restrict__ xn,
                const float* __restrict__ a2w,
                const float* __restrict__ a2b) {
    extern __shared__ char sm[];
    float*  Wn_s = (float*)(sm + 73728);
    float*  a_sa = (float*)(sm + 77824);

    const int tid  = threadIdx.x;
    const int wid  = tid >> 5;
    const int lane = tid & 31;
    const int nI   = lane & 7;
    const int hI   = lane >> 3;
    const int cq   = lane & 15;
    const int rh   = lane >> 4;

    float* a_s = a_sa + wid * 36;

    for (int i = tid; i < 1024; i += 128) Wn_s[i] = WnP_g[i];
    // zero row 35 (pad) of both stages, all warps
    for (int i = tid; i < 128; i += 128) { /* 4w * 2st * 16 chunks = 128 */ }
    {
        int w = tid >> 5, rem = tid & 31;
        int st = rem >> 4, l = rem & 15;
        float4* pad = (float4*)(sm + w * 18432 + st * 9216);
        pad[560 + l] = make_float4(0.f, 0.f, 0.f, 0.f);
    }

    float4 a2v = __ldg((const float4*)a2w + hI);
    const float a2r0 = a2v.x, a2r1 = a2v.y, a2r2 = a2v.z, a2r3 = a2v.w;
    const float b2 = __ldg(a2b);
    const unsigned wn_base = (unsigned)__cvta_generic_to_shared(Wn_s);
    const unsigned x_base  = (unsigned)__cvta_generic_to_shared(sm) + wid * 18432;

    __syncthreads();

    // ---- prologue: prefetch first tile into stage 0
    {
        const float4* src4 = (const float4*)xn + (size_t)(blockIdx.x * 4 + wid) * 560;
#pragma unroll
        for (int k = 0; k < 18; k++) {
            int idx = k * 32 + lane;
            if (idx < 560) {
                int row = idx >> 4, c4 = idx & 15;
                cp16(x_base + (unsigned)(row * 16 + (c4 ^ (row & 7))) * 16, src4 + idx);
            }
        }
        cp_commit();
    }

    int st = 0;
    for (int g = blockIdx.x; g < 16384; g += GRID) {
        const int b = g * 4 + wid;

        // ---- prefetch next tile into other stage
        {
            int gn = g + GRID;
            if (gn < 16384) {
                const float4* src4 = (const float4*)xn + (size_t)(gn * 4 + wid) * 560;
                unsigned dst = x_base + (unsigned)(st ^ 1) * 9216;
#pragma unroll
                for (int k = 0; k < 18; k++) {
                    int idx = k * 32 + lane;
                    if (idx < 560) {
                        int row = idx >> 4, c4 = idx & 15;
                        cp16(dst + (unsigned)(row * 16 + (c4 ^ (row & 7))) * 16, src4 + idx);
                    }
                }
            }
            cp_commit();
        }

        // ---- eb for current tile (hoisted; consumed in phase 3)
        float4 ebv = __ldg((const float4*)eb_g + (size_t)b * 4 + hI);

        // ---- wait for current tile, then compute
        cp_wait1();
        __syncwarp();

        float4* xw4 = (float4*)(sm + wid * 18432 + st * 9216);

        // ---- phase 2: u[j][h0..h3] = (Wn @ x_row)[4hI..], rows nI + 8j
        ull u2[5][2];
#pragma unroll
        for (int j = 0; j < 5; j++) { u2[j][0] = 0ull; u2[j][1] = 0ull; }
        const bool has2 = (nI < 3);
        const int row4 = has2 ? (nI + 32) : 35;   // row 35 is zeroed pad

#pragma unroll 4
        for (int p4 = 0; p4 < 16; p4++) {
            ull wl[4], wh[4];
#pragma unroll
            for (int cc = 0; cc < 4; cc++)
                lds_v2u64(wl[cc], wh[cc], wn_base + ((4 * p4 + cc) * 16 + 4 * hI) * 4);
#pragma unroll
            for (int j = 0; j < 5; j++) {
                int row = (j < 4) ? (nI + 8 * j) : row4;
                float4 xv = xw4[row * 16 + (p4 ^ (row & 7))];
                ull a0 = splat2(xv.x), a1 = splat2(xv.y);
                ull a2_ = splat2(xv.z), a3 = splat2(xv.w);
                fma2(u2[j][0], a0,  wl[0]); fma2(u2[j][1], a0,  wh[0]);
                fma2(u2[j][0], a1,  wl[1]); fma2(u2[j][1], a1,  wh[1]);
                fma2(u2[j][0], a2_, wl[2]); fma2(u2[j][1], a2_, wh[2]);
                fma2(u2[j][0], a3,  wl[3]); fma2(u2[j][1], a3,  wh[3]);
            }
        }

        // ---- phase 3: e, leaky relu, softmax over n
        float e[5];
#pragma unroll
        for (int j = 0; j < 5; j++) {
            float2 lo = unpack2(u2[j][0]), hi = unpack2(u2[j][1]);
            float pe;
            pe =      a2r0 * fmaxf(lo.x + ebv.x, 0.f);
            pe = fmaf(a2r1,  fmaxf(lo.y + ebv.y, 0.f), pe);
            pe = fmaf(a2r2,  fmaxf(hi.x + ebv.z, 0.f), pe);
            pe = fmaf(a2r3,  fmaxf(hi.y + ebv.w, 0.f), pe);
            pe += __shfl_xor_sync(0xffffffffu, pe, 8);
            pe += __shfl_xor_sync(0xffffffffu, pe, 16);
            float ev = pe + b2;
            e[j] = ev > 0.f ? ev : 0.2f * ev;
        }
        if (!has2) e[4] = -INFINITY;

        float mx = e[0];
#pragma unroll
        for (int j = 1; j < 5; j++) mx = fmaxf(mx, e[j]);
#pragma unroll
        for (int m = 1; m <= 4; m <<= 1) mx = fmaxf(mx, __shfl_xor_sync(0xffffffffu, mx, m));

        float ax[5]; float sum = 0.f;
#pragma unroll
        for (int j = 0; j < 5; j++) { ax[j] = __expf(e[j] - mx); sum += ax[j]; }
#pragma unroll
        for (int m = 1; m <= 4; m <<= 1) sum += __shfl_xor_sync(0xffffffffu, sum, m);
        float rinv = 1.0f / sum;

        if (hI == 0) {
#pragma unroll
            for (int j = 0; j < 4; j++) a_s[nI + 8 * j] = ax[j] * rinv;
            if (has2) a_s[nI + 32] = ax[4] * rinv;
            if (nI == 3) a_s[35] = 0.f;   // pad row weight
        }
        __syncwarp();

        // ---- phase 4: s[c] = sum_n a_n x_n[c]; lane=(cq,rh): 4 c x 18 rows
        float2 ap[9];
#pragma unroll
        for (int i = 0; i < 9; i++) ap[i] = *(const float2*)&a_s[rh * 18 + 2 * i];

        float4 acc = make_float4(0.f, 0.f, 0.f, 0.f);
#pragma unroll
        for (int q = 0; q < 18; q++) {
            int row = rh * 18 + q;                 // row 35 contributes 0 (a=0, x=0)
            float a = (q & 1) ? ap[q >> 1].y : ap[q >> 1].x;
            float4 xv = xw4[row * 16 + (cq ^ (row & 7))];
            acc.x = fmaf(a, xv.x, acc.x);
            acc.y = fmaf(a, xv.y, acc.y);
            acc.z = fmaf(a, xv.z, acc.z);
            acc.w = fmaf(a, xv.w, acc.w);
        }
        acc.x += __shfl_xor_sync(0xffffffffu, acc.x, 16);
        acc.y += __shfl_xor_sync(0xffffffffu, acc.y, 16);
        acc.z += __shfl_xor_sync(0xffffffffu, acc.z, 16);
        acc.w += __shfl_xor_sync(0xffffffffu, acc.w, 16);
        if (rh == 0)
            *((float4*)(s_g + (size_t)b * 64) + cq) = acc;
        __syncwarp();   // all lanes done reading stage st before it is overwritten

        st ^= 1;
    }
}

// ---------------- K4: out = elu(align_w @ s + align_b) ----------------
#define OPITCH 68
__global__ __launch_bounds__(256)
void out_kernel(const float* __restrict__ aw,
                const float* __restrict__ abv,
                float* __restrict__ out) {
    __shared__ __align__(16) float s_s[64 * OPITCH];
    __shared__ __align__(16) float w_t[64 * OPITCH];
    __shared__ float ab_s[64];

    const int tid = threadIdx.x;
    const int b0  = blockIdx.x * 64;

#pragma unroll
    for (int k = 0; k < 16; k++) {
        int idx = k * 256 + tid;
        int d = idx >> 6, c = idx & 63;
        w_t[c * OPITCH + d] = aw[idx];
    }
    if (tid < 64) ab_s[tid] = abv[tid];

#pragma unroll
    for (int k = 0; k < 4; k++) {
        int idx4 = k * 256 + tid;
        int bl = idx4 >> 4, c4 = idx4 & 15;
        *(float4*)&s_s[bl * OPITCH + c4 * 4] =
            ((const float4*)(s_g + (size_t)(b0 + bl) * 64))[c4];
    }
    __syncthreads();

    const int tx = tid & 15;
    const int ty = tid >> 4;

    ull acc2[4][2];
#pragma unroll
    for (int bi = 0; bi < 4; bi++) { acc2[bi][0] = 0ull; acc2[bi][1] = 0ull; }

#pragma unroll
    for (int cs = 0; cs < 16; cs++) {
        ull wv[4][2];
#pragma unroll
        for (int j = 0; j < 4; j++) {
            const float* wp = &w_t[(4 * cs + j) * OPITCH + 4 * tx];
            wv[j][0] = *(const ull*)&wp[0];
            wv[j][1] = *(const ull*)&wp[2];
        }
#pragma unroll
        for (int bi = 0; bi < 4; bi++) {
            float4 sv = *(const float4*)&s_s[(4 * ty + bi) * OPITCH + 4 * cs];
            ull a0 = splat2(sv.x), a1 = splat2(sv.y);
            ull a2 = splat2(sv.z), a3 = splat2(sv.w);
            fma2(acc2[bi][0], a0, wv[0][0]); fma2(acc2[bi][1], a0, wv[0][1]);
            fma2(acc2[bi][0], a1, wv[1][0]); fma2(acc2[bi][1], a1, wv[1][1]);
            fma2(acc2[bi][0], a2, wv[2][0]); fma2(acc2[bi][1], a2, wv[2][1]);
            fma2(acc2[bi][0], a3, wv[3][0]); fma2(acc2[bi][1], a3, wv[3][1]);
        }
    }

    float4 abv4 = *(const float4*)&ab_s[4 * tx];
#pragma unroll
    for (int bi = 0; bi < 4; bi++) {
        float2 lo = unpack2(acc2[bi][0]), hi = unpack2(acc2[bi][1]);
        float4 o;
        o.x = lo.x + abv4.x; o.x = (o.x > 0.f) ? o.x : expm1f(o.x);
        o.y = lo.y + abv4.y; o.y = (o.y > 0.f) ? o.y : expm1f(o.y);
        o.z = hi.x + abv4.z; o.z = (o.z > 0.f) ? o.z : expm1f(o.z);
        o.w = hi.y + abv4.w; o.w = (o.w > 0.f) ? o.w : expm1f(o.w);
        *(float4*)&out[(size_t)(b0 + 4 * ty + bi) * 64 + 4 * tx] = o;
    }
}

extern "C" void kernel_launch(void* const* d_in, const int* in_sizes, int n_in,
                              void* d_out, int out_size) {
    const float* x_target = (const float*)d_in[0];
    const float* x_neigh  = (const float*)d_in[1];
    const float* align_w  = (const float*)d_in[2];
    const float* align_b  = (const float*)d_in[3];
    const float* attn1_w  = (const float*)d_in[4];
    const float* attn1_b  = (const float*)d_in[5];
    const float* attn2_w  = (const float*)d_in[6];
    const float* attn2_b  = (const float*)d_in[7];
    float* out = (float*)d_out;

    static bool attr_set = false;
    if (!attr_set) {
        cudaFuncSetAttribute(gat_kernel, cudaFuncAttributeMaxDynamicSharedMemorySize, 78400);
        attr_set = true;
    }

    prep_kernel<<<9, 128>>>(align_w, align_b, attn1_w, attn1_b);
    eb_kernel<<<8192, 128>>>(x_target);
    gat_kernel<<<GRID, 128, 78400>>>(x_neigh, attn2_w, attn2_b);
    out_kernel<<<1024, 256>>>(align_w, align_b, out);
}

// round 15
// speedup vs baseline: 1.5640x; 1.3296x over previous
#include <cuda_runtime.h>
#include <math.h>

// GAT layer, algebraically folded + fissioned:
//  K1 prep : Wn = attn1_w[:,64:]@align_w, Wt = attn1_w[:,:64]@align_w,
//            cb = (attn1_w[:,:64]+attn1_w[:,64:])@align_b + attn1_b
//  K2 eb   : eb[b] = Wt @ x_t[b] + cb                     (65536 x 16)
//  K3 main : e_n = leaky(attn2 @ relu(Wn x_n + eb) + b2); a = softmax(e);
//            s[b] = sum_n a_n x_n                          (65536 x 64)
//            -- phase-2 GEMM via mma.sync tf32 (HMMA), weights register-
//               resident as B fragments; cp.async 2-stage ping-pong.
//  K4 out  : out = elu(align_w @ s + align_b)   [smem-tiled GEMM, f32x2]

#define GRID 296
typedef unsigned long long ull;

__device__ float WnP_g[1024];
__device__ float WtP_g[1024];
__device__ float CBP_g[16];
__device__ float eb_g[65536 * 16];     // 4 MB scratch
__device__ float s_g[65536 * 64];      // 16 MB scratch

__device__ __forceinline__ ull splat2(float a) {
    ull r; asm("mov.b64 %0, {%1, %1};" : "=l"(r) : "f"(a)); return r;
}
__device__ __forceinline__ void fma2(ull& acc, ull a, ull b) {
    asm("fma.rn.f32x2 %0, %1, %2, %0;" : "+l"(acc) : "l"(a), "l"(b));
}
__device__ __forceinline__ float2 unpack2(ull v) {
    float2 r; asm("mov.b64 {%0, %1}, %2;" : "=f"(r.x), "=f"(r.y) : "l"(v)); return r;
}
__device__ __forceinline__ void cp16(unsigned dst, const void* src) {
    asm volatile("cp.async.cg.shared.global [%0], [%1], 16;" :: "r"(dst), "l"(src));
}
__device__ __forceinline__ void cp_commit() {
    asm volatile("cp.async.commit_group;");
}
__device__ __forceinline__ void cp_wait1() {
    asm volatile("cp.async.wait_group 1;");
}
__device__ __forceinline__ unsigned f2tf(float f) {
    unsigned r; asm("cvt.rna.tf32.f32 %0, %1;" : "=r"(r) : "f"(f)); return r;
}
// D += A@B for m16n8k8 tf32; c[4] fp32 accumulators
__device__ __forceinline__ void mma_tf32(float* c, unsigned a0, unsigned a1,
                                         unsigned a2, unsigned a3,
                                         unsigned b0, unsigned b1) {
    asm("mma.sync.aligned.m16n8k8.row.col.f32.tf32.tf32.f32 "
        "{%0,%1,%2,%3}, {%4,%5,%6,%7}, {%8,%9}, {%0,%1,%2,%3};"
        : "+f"(c[0]), "+f"(c[1]), "+f"(c[2]), "+f"(c[3])
        : "r"(a0), "r"(a1), "r"(a2), "r"(a3), "r"(b0), "r"(b1));
}

// ---------------- K1: fold weights ----------------
__global__ void prep_kernel(const float* __restrict__ align_w,
                            const float* __restrict__ align_b,
                            const float* __restrict__ a1w,
                            const float* __restrict__ a1b) {
    int idx = blockIdx.x * blockDim.x + threadIdx.x;
    if (idx < 1024) {
        int c = idx >> 4, h = idx & 15;
        float st = 0.f, sn = 0.f;
        for (int d = 0; d < 64; d++) {
            float aw = align_w[d * 64 + c];
            st = fmaf(a1w[h * 128 + d],      aw, st);
            sn = fmaf(a1w[h * 128 + 64 + d], aw, sn);
        }
        WtP_g[c * 16 + h] = st;
        WnP_g[c * 16 + h] = sn;
    } else if (idx < 1040) {
        int h = idx - 1024;
        float s = 0.f;
        for (int d = 0; d < 64; d++)
            s += (a1w[h * 128 + d] + a1w[h * 128 + 64 + d]) * align_b[d];
        CBP_g[h] = s + a1b[h];
    }
}

// ---------------- K2: eb[b] = Wt @ x_t[b] + cb ----------------
__global__ __launch_bounds__(128) void eb_kernel(const float* __restrict__ xt) {
    __shared__ float xs[512];
    __shared__ float wt[1024];
    __shared__ float cbs[16];
    const int tid = threadIdx.x;
    for (int i = tid; i < 1024; i += 128) wt[i] = WtP_g[i];
    if (tid < 16) cbs[tid] = CBP_g[tid];
    const int b0 = blockIdx.x * 8;
    for (int i = tid; i < 512; i += 128) xs[i] = xt[(size_t)b0 * 64 + i];
    __syncthreads();
    const int bl = tid >> 4, h = tid & 15;
    float acc = 0.f;
#pragma unroll 8
    for (int c = 0; c < 64; c++) acc = fmaf(xs[bl * 64 + c], wt[c * 16 + h], acc);
    eb_g[(size_t)(b0 + bl) * 16 + h] = acc + cbs[h];
}

// ---------------- K3: main (attention + weighted sum) ----------------
// dynamic smem (98944 B):
//   [0     ) float4 x[4 warps][2 stages][48 rows][16 chunks]   98304
//            rows 0..34 = neighbors (cp.async, swizzled); 35..47 zero pad
//   [98304 ) float a_s[4][36]                                    576
__global__ __launch_bounds__(128, 2)
void gat_kernel(const float* __restrict__ xn,
                const float* __restrict__ a2w,
                const float* __restrict__ a2b) {
    extern __shared__ char sm[];
    float* a_sa = (float*)(sm + 98304);

    const int tid  = threadIdx.x;
    const int wid  = tid >> 5;
    const int lane = tid & 31;
    const int q    = lane >> 2;      // mma group id (row-within-8)
    const int t    = lane & 3;       // mma thread-in-group (col)
    const int cq   = lane & 15;      // phase-4 c-chunk
    const int rh   = lane >> 4;      // phase-4 row-half

    float* a_s = a_sa + wid * 36;
    char*  xbase_c = sm + wid * 24576;
    const unsigned x_smem = (unsigned)__cvta_generic_to_shared(xbase_c);

    // zero pad rows 35..47, both stages (persist; cp.async writes rows 0..34 only)
    {
        float4 z = make_float4(0.f, 0.f, 0.f, 0.f);
        float4* p = (float4*)xbase_c;
        for (int i = lane; i < 208; i += 32) { p[560 + i] = z; p[768 + 560 + i] = z; }
    }

    // B fragments (folded Wn as tf32), register-resident for the whole kernel.
    // b0 = Wn[kt*8 + t][nt*8 + q], b1 = Wn[kt*8 + t + 4][nt*8 + q]
    unsigned bfr[2][8][2];
#pragma unroll
    for (int nt = 0; nt < 2; nt++)
#pragma unroll
        for (int kt = 0; kt < 8; kt++) {
            bfr[nt][kt][0] = f2tf(WnP_g[(kt * 8 + t) * 16 + nt * 8 + q]);
            bfr[nt][kt][1] = f2tf(WnP_g[(kt * 8 + t + 4) * 16 + nt * 8 + q]);
        }

    // attn2 weights for this lane's 4 h's: {2t, 2t+1, 8+2t, 8+2t+1}
    const float2 a2lo = __ldg((const float2*)(a2w + 2 * t));
    const float2 a2hi = __ldg((const float2*)(a2w + 8 + 2 * t));
    const float  b2   = __ldg(a2b);

    __syncwarp();

    // ---- prologue: prefetch first tile into stage 0
    {
        const float4* src4 = (const float4*)xn + (size_t)(blockIdx.x * 4 + wid) * 560;
#pragma unroll
        for (int k = 0; k < 18; k++) {
            int idx = k * 32 + lane;
            if (idx < 560) {
                int row = idx >> 4, c4 = idx & 15;
                cp16(x_smem + (unsigned)(row * 16 + (c4 ^ (row & 7))) * 16, src4 + idx);
            }
        }
        cp_commit();
    }

    int st = 0;
    for (int g = blockIdx.x; g < 16384; g += GRID) {
        const int b = g * 4 + wid;

        // ---- prefetch next tile into other stage
        {
            int gn = g + GRID;
            if (gn < 16384) {
                const float4* src4 = (const float4*)xn + (size_t)(gn * 4 + wid) * 560;
                unsigned dst = x_smem + (unsigned)(st ^ 1) * 12288;
#pragma unroll
                for (int k = 0; k < 18; k++) {
                    int idx = k * 32 + lane;
                    if (idx < 560) {
                        int row = idx >> 4, c4 = idx & 15;
                        cp16(dst + (unsigned)(row * 16 + (c4 ^ (row & 7))) * 16, src4 + idx);
                    }
                }
            }
            cp_commit();
        }

        // ---- eb for current tile (hoisted; consumed after mma)
        const float2 eb0 = __ldg((const float2*)(eb_g + (size_t)b * 16 + 2 * t));
        const float2 eb1 = __ldg((const float2*)(eb_g + (size_t)b * 16 + 8 + 2 * t));

        // ---- wait for current tile
        cp_wait1();
        __syncwarp();

        const float*  xw  = (const float*)(xbase_c + st * 12288);
        const float4* xw4 = (const float4*)xw;

        // ---- phase 2: u[48 x 16] = x @ Wn via 48x tf32 mma
        float cfr[3][2][4];
#pragma unroll
        for (int mt = 0; mt < 3; mt++)
#pragma unroll
            for (int nt = 0; nt < 2; nt++)
#pragma unroll
                for (int k = 0; k < 4; k++) cfr[mt][nt][k] = 0.f;

#pragma unroll
        for (int mt = 0; mt < 3; mt++) {
            const float* xr = xw + (mt * 16 + q) * 64 + t;   // (r&7)==q for all mt
#pragma unroll
            for (int kt = 0; kt < 8; kt++) {
                int o0 = ((2 * kt) ^ q) * 4;    // swizzled chunk for cols kt*8+t
                int o2 = o0 ^ 4;                 // cols kt*8+t+4
                unsigned a0 = f2tf(xr[o0]),       a1 = f2tf(xr[o0 + 512]);
                unsigned a2 = f2tf(xr[o2]),       a3 = f2tf(xr[o2 + 512]);
                mma_tf32(cfr[mt][0], a0, a1, a2, a3, bfr[0][kt][0], bfr[0][kt][1]);
                mma_tf32(cfr[mt][1], a0, a1, a2, a3, bfr[1][kt][0], bfr[1][kt][1]);
            }
        }

        // ---- phase 3: e per row from fragments, softmax over n (rows 0..34)
        // lane holds rows {mt*16+q, mt*16+8+q}, h = {2t,2t+1,8+2t,8+2t+1}
        float e[6];
#pragma unroll
        for (int mt = 0; mt < 3; mt++) {
            float plo, phi;
            plo =      a2lo.x * fmaxf(cfr[mt][0][0] + eb0.x, 0.f);
            plo = fmaf(a2lo.y,  fmaxf(cfr[mt][0][1] + eb0.y, 0.f), plo);
            plo = fmaf(a2hi.x,  fmaxf(cfr[mt][1][0] + eb1.x, 0.f), plo);
            plo = fmaf(a2hi.y,  fmaxf(cfr[mt][1][1] + eb1.y, 0.f), plo);
            phi =      a2lo.x * fmaxf(cfr[mt][0][2] + eb0.x, 0.f);
            phi = fmaf(a2lo.y,  fmaxf(cfr[mt][0][3] + eb0.y, 0.f), phi);
            phi = fmaf(a2hi.x,  fmaxf(cfr[mt][1][2] + eb1.x, 0.f), phi);
            phi = fmaf(a2hi.y,  fmaxf(cfr[mt][1][3] + eb1.y, 0.f), phi);
            // sum over 16 h: reduce across the 4-lane quad (t axis)
            plo += __shfl_xor_sync(0xffffffffu, plo, 1);
            plo += __shfl_xor_sync(0xffffffffu, plo, 2);
            phi += __shfl_xor_sync(0xffffffffu, phi, 1);
            phi += __shfl_xor_sync(0xffffffffu, phi, 2);
            float elo = plo + b2; elo = (elo > 0.f) ? elo : 0.2f * elo;
            float ehi = phi + b2; ehi = (ehi > 0.f) ? ehi : 0.2f * ehi;
            int rlo = mt * 16 + q;
            e[2 * mt]     = (rlo < 35)     ? elo : -INFINITY;
            e[2 * mt + 1] = (rlo + 8 < 35) ? ehi : -INFINITY;
        }

        // warp softmax: reduce across q only (xor 4,8,16) — each row counted once
        float mx = e[0];
#pragma unroll
        for (int j = 1; j < 6; j++) mx = fmaxf(mx, e[j]);
        mx = fmaxf(mx, __shfl_xor_sync(0xffffffffu, mx, 4));
        mx = fmaxf(mx, __shfl_xor_sync(0xffffffffu, mx, 8));
        mx = fmaxf(mx, __shfl_xor_sync(0xffffffffu, mx, 16));

        float ax[6]; float sum = 0.f;
#pragma unroll
        for (int j = 0; j < 6; j++) { ax[j] = __expf(e[j] - mx); sum += ax[j]; }
        sum += __shfl_xor_sync(0xffffffffu, sum, 4);
        sum += __shfl_xor_sync(0xffffffffu, sum, 8);
        sum += __shfl_xor_sync(0xffffffffu, sum, 16);
        const float rinv = 1.0f / sum;

        if (t == 0) {
#pragma unroll
            for (int mt = 0; mt < 3; mt++) {
                int rlo = mt * 16 + q, rhi = rlo + 8;
                if (rlo < 35) a_s[rlo] = ax[2 * mt] * rinv;
                else if (rlo == 35) a_s[35] = 0.f;
                if (rhi < 35) a_s[rhi] = ax[2 * mt + 1] * rinv;
                else if (rhi == 35) a_s[35] = 0.f;
            }
        }
        __syncwarp();

        // ---- phase 4: s[c] = sum_n a_n x_n[c]; fp32 tile; lane=(cq,rh)
        float2 ap[9];
#pragma unroll
        for (int i = 0; i < 9; i++) ap[i] = *(const float2*)&a_s[rh * 18 + 2 * i];

        float4 acc = make_float4(0.f, 0.f, 0.f, 0.f);
#pragma unroll
        for (int p = 0; p < 18; p++) {
            int row = rh * 18 + p;                 // row 35 contributes 0 (a=0, x=0)
            float a = (p & 1) ? ap[p >> 1].y : ap[p >> 1].x;
            float4 xv = xw4[row * 16 + (cq ^ (row & 7))];
            acc.x = fmaf(a, xv.x, acc.x);
            acc.y = fmaf(a, xv.y, acc.y);
            acc.z = fmaf(a, xv.z, acc.z);
            acc.w = fmaf(a, xv.w, acc.w);
        }
        acc.x += __shfl_xor_sync(0xffffffffu, acc.x, 16);
        acc.y += __shfl_xor_sync(0xffffffffu, acc.y, 16);
        acc.z += __shfl_xor_sync(0xffffffffu, acc.z, 16);
        acc.w += __shfl_xor_sync(0xffffffffu, acc.w, 16);
        if (rh == 0)
            *((float4*)(s_g + (size_t)b * 64) + cq) = acc;
        __syncwarp();   // all lanes done with stage st before it is overwritten

        st ^= 1;
    }
}

// ---------------- K4: out = elu(align_w @ s + align_b) ----------------
#define OPITCH 68
__global__ __launch_bounds__(256)
void out_kernel(const float* __restrict__ aw,
                const float* __restrict__ abv,
                float* __restrict__ out) {
    __shared__ __align__(16) float s_s[64 * OPITCH];
    __shared__ __align__(16) float w_t[64 * OPITCH];
    __shared__ float ab_s[64];

    const int tid = threadIdx.x;
    const int b0  = blockIdx.x * 64;

#pragma unroll
    for (int k = 0; k < 16; k++) {
        int idx = k * 256 + tid;
        int d = idx >> 6, c = idx & 63;
        w_t[c * OPITCH + d] = aw[idx];
    }
    if (tid < 64) ab_s[tid] = abv[tid];

#pragma unroll
    for (int k = 0; k < 4; k++) {
        int idx4 = k * 256 + tid;
        int bl = idx4 >> 4, c4 = idx4 & 15;
        *(float4*)&s_s[bl * OPITCH + c4 * 4] =
            ((const float4*)(s_g + (size_t)(b0 + bl) * 64))[c4];
    }
    __syncthreads();

    const int tx = tid & 15;
    const int ty = tid >> 4;

    ull acc2[4][2];
#pragma unroll
    for (int bi = 0; bi < 4; bi++) { acc2[bi][0] = 0ull; acc2[bi][1] = 0ull; }

#pragma unroll
    for (int cs = 0; cs < 16; cs++) {
        ull wv[4][2];
#pragma unroll
        for (int j = 0; j < 4; j++) {
            const float* wp = &w_t[(4 * cs + j) * OPITCH + 4 * tx];
            wv[j][0] = *(const ull*)&wp[0];
            wv[j][1] = *(const ull*)&wp[2];
        }
#pragma unroll
        for (int bi = 0; bi < 4; bi++) {
            float4 sv = *(const float4*)&s_s[(4 * ty + bi) * OPITCH + 4 * cs];
            ull a0 = splat2(sv.x), a1 = splat2(sv.y);
            ull a2 = splat2(sv.z), a3 = splat2(sv.w);
            fma2(acc2[bi][0], a0, wv[0][0]); fma2(acc2[bi][1], a0, wv[0][1]);
            fma2(acc2[bi][0], a1, wv[1][0]); fma2(acc2[bi][1], a1, wv[1][1]);
            fma2(acc2[bi][0], a2, wv[2][0]); fma2(acc2[bi][1], a2, wv[2][1]);
            fma2(acc2[bi][0], a3, wv[3][0]); fma2(acc2[bi][1], a3, wv[3][1]);
        }
    }

    float4 abv4 = *(const float4*)&ab_s[4 * tx];
#pragma unroll
    for (int bi = 0; bi < 4; bi++) {
        float2 lo = unpack2(acc2[bi][0]), hi = unpack2(acc2[bi][1]);
        float4 o;
        o.x = lo.x + abv4.x; o.x = (o.x > 0.f) ? o.x : expm1f(o.x);
        o.y = lo.y + abv4.y; o.y = (o.y > 0.f) ? o.y : expm1f(o.y);
        o.z = hi.x + abv4.z; o.z = (o.z > 0.f) ? o.z : expm1f(o.z);
        o.w = hi.y + abv4.w; o.w = (o.w > 0.f) ? o.w : expm1f(o.w);
        *(float4*)&out[(size_t)(b0 + 4 * ty + bi) * 64 + 4 * tx] = o;
    }
}

extern "C" void kernel_launch(void* const* d_in, const int* in_sizes, int n_in,
                              void* d_out, int out_size) {
    const float* x_target = (const float*)d_in[0];
    const float* x_neigh  = (const float*)d_in[1];
    const float* align_w  = (const float*)d_in[2];
    const float* align_b  = (const float*)d_in[3];
    const float* attn1_w  = (const float*)d_in[4];
    const float* attn1_b  = (const float*)d_in[5];
    const float* attn2_w  = (const float*)d_in[6];
    const float* attn2_b  = (const float*)d_in[7];
    float* out = (float*)d_out;

    static bool attr_set = false;
    if (!attr_set) {
        cudaFuncSetAttribute(gat_kernel, cudaFuncAttributeMaxDynamicSharedMemorySize, 98944);
        attr_set = true;
    }

    prep_kernel<<<9, 128>>>(align_w, align_b, attn1_w, attn1_b);
    eb_kernel<<<8192, 128>>>(x_target);
    gat_kernel<<<GRID, 128, 98944>>>(x_neigh, attn2_w, attn2_b);
    out_kernel<<<1024, 256>>>(align_w, align_b, out);
}

// round 16
// speedup vs baseline: 1.7759x; 1.1354x over previous
#include <cuda_runtime.h>
#include <math.h>

// GAT layer, algebraically folded + fissioned:
//  K1 prep : Wn = attn1_w[:,64:]@align_w, Wt = attn1_w[:,:64]@align_w,
//            cb = (attn1_w[:,:64]+attn1_w[:,64:])@align_b + attn1_b
//  K2 eb   : eb[b] = Wt @ x_t[b] + cb                     (65536 x 16)
//  K3 main : e_n = leaky(attn2 @ relu(Wn x_n + eb) + b2); a = softmax(e);
//            s[b] = sum_n a_n x_n                          (65536 x 64)
//            -- tf32 mma.sync phase-2, 36-row tiles (mt=2 handled with
//               clamped/zero A-frags) -> 74.3 KB smem -> 3 CTAs/SM.
//  K4 out  : out = elu(align_w @ s + align_b)   [128-batch tiled GEMM]

#define GRID 444
typedef unsigned long long ull;

__device__ float WnP_g[1024];
__device__ float WtP_g[1024];
__device__ float CBP_g[16];
__device__ float eb_g[65536 * 16];     // 4 MB scratch
__device__ float s_g[65536 * 64];      // 16 MB scratch

__device__ __forceinline__ ull splat2(float a) {
    ull r; asm("mov.b64 %0, {%1, %1};" : "=l"(r) : "f"(a)); return r;
}
__device__ __forceinline__ void fma2(ull& acc, ull a, ull b) {
    asm("fma.rn.f32x2 %0, %1, %2, %0;" : "+l"(acc) : "l"(a), "l"(b));
}
__device__ __forceinline__ float2 unpack2(ull v) {
    float2 r; asm("mov.b64 {%0, %1}, %2;" : "=f"(r.x), "=f"(r.y) : "l"(v)); return r;
}
__device__ __forceinline__ void cp16(unsigned dst, const void* src) {
    asm volatile("cp.async.cg.shared.global [%0], [%1], 16;" :: "r"(dst), "l"(src));
}
__device__ __forceinline__ void cp_commit() {
    asm volatile("cp.async.commit_group;");
}
__device__ __forceinline__ void cp_wait1() {
    asm volatile("cp.async.wait_group 1;");
}
__device__ __forceinline__ unsigned f2tf(float f) {
    unsigned r; asm("cvt.rna.tf32.f32 %0, %1;" : "=r"(r) : "f"(f)); return r;
}
// D += A@B for m16n8k8 tf32; c[4] fp32 accumulators
__device__ __forceinline__ void mma_tf32(float* c, unsigned a0, unsigned a1,
                                         unsigned a2, unsigned a3,
                                         unsigned b0, unsigned b1) {
    asm("mma.sync.aligned.m16n8k8.row.col.f32.tf32.tf32.f32 "
        "{%0,%1,%2,%3}, {%4,%5,%6,%7}, {%8,%9}, {%0,%1,%2,%3};"
        : "+f"(c[0]), "+f"(c[1]), "+f"(c[2]), "+f"(c[3])
        : "r"(a0), "r"(a1), "r"(a2), "r"(a3), "r"(b0), "r"(b1));
}

// ---------------- K1: fold weights ----------------
__global__ void prep_kernel(const float* __restrict__ align_w,
                            const float* __restrict__ align_b,
                            const float* __restrict__ a1w,
                            const float* __restrict__ a1b) {
    int idx = blockIdx.x * blockDim.x + threadIdx.x;
    if (idx < 1024) {
        int c = idx >> 4, h = idx & 15;
        float st = 0.f, sn = 0.f;
        for (int d = 0; d < 64; d++) {
            float aw = align_w[d * 64 + c];
            st = fmaf(a1w[h * 128 + d],      aw, st);
            sn = fmaf(a1w[h * 128 + 64 + d], aw, sn);
        }
        WtP_g[c * 16 + h] = st;
        WnP_g[c * 16 + h] = sn;
    } else if (idx < 1040) {
        int h = idx - 1024;
        float s = 0.f;
        for (int d = 0; d < 64; d++)
            s += (a1w[h * 128 + d] + a1w[h * 128 + 64 + d]) * align_b[d];
        CBP_g[h] = s + a1b[h];
    }
}

// ---------------- K2: eb[b] = Wt @ x_t[b] + cb ----------------
// 32 batches/block, each thread 4 independent accumulation chains.
__global__ __launch_bounds__(128) void eb_kernel(const float* __restrict__ xt) {
    __shared__ float xs[2048];
    __shared__ float wt[1024];
    __shared__ float cbs[16];
    const int tid = threadIdx.x;
    for (int i = tid; i < 1024; i += 128) wt[i] = WtP_g[i];
    if (tid < 16) cbs[tid] = CBP_g[tid];
    const int b0 = blockIdx.x * 32;
    {
        const float4* src = (const float4*)(xt + (size_t)b0 * 64);
#pragma unroll
        for (int k = 0; k < 4; k++) ((float4*)xs)[k * 128 + tid] = src[k * 128 + tid];
    }
    __syncthreads();
    const int h = tid & 15, bl = tid >> 4;   // bl 0..7
    float a0 = 0.f, a1 = 0.f, a2 = 0.f, a3 = 0.f;
#pragma unroll 8
    for (int c = 0; c < 64; c++) {
        float w = wt[c * 16 + h];
        a0 = fmaf(xs[bl * 64 + c],        w, a0);
        a1 = fmaf(xs[(bl + 8) * 64 + c],  w, a1);
        a2 = fmaf(xs[(bl + 16) * 64 + c], w, a2);
        a3 = fmaf(xs[(bl + 24) * 64 + c], w, a3);
    }
    float cb = cbs[h];
    eb_g[(size_t)(b0 + bl) * 16 + h]      = a0 + cb;
    eb_g[(size_t)(b0 + bl + 8) * 16 + h]  = a1 + cb;
    eb_g[(size_t)(b0 + bl + 16) * 16 + h] = a2 + cb;
    eb_g[(size_t)(b0 + bl + 24) * 16 + h] = a3 + cb;
}

// ---------------- K3: main (attention + weighted sum) ----------------
// dynamic smem (74304 B):
//   [0     ) float4 x[4 warps][2 stages][36 rows][16 chunks]   73728
//            rows 0..34 = neighbors (cp.async, swizzled); row 35 zero pad
//   [73728 ) float a_s[4][36]                                    576
__global__ __launch_bounds__(128, 3)
void gat_kernel(const float* __restrict__ xn,
                const float* __restrict__ a2w,
                const float* __restrict__ a2b) {
    extern __shared__ char sm[];
    float* a_sa = (float*)(sm + 73728);

    const int tid  = threadIdx.x;
    const int wid  = tid >> 5;
    const int lane = tid & 31;
    const int q    = lane >> 2;      // mma group id (row-within-8)
    const int t    = lane & 3;       // mma thread-in-group (col)
    const int cq   = lane & 15;      // phase-4 c-chunk
    const int rh   = lane >> 4;      // phase-4 row-half

    float* a_s = a_sa + wid * 36;
    char*  xbase_c = sm + wid * 18432;
    const unsigned x_smem = (unsigned)__cvta_generic_to_shared(xbase_c);

    // zero pad row 35, both stages (persist; cp.async writes rows 0..34 only)
    if (lane < 16) {
        float4 z = make_float4(0.f, 0.f, 0.f, 0.f);
        float4* p = (float4*)xbase_c;
        p[560 + lane] = z;            // stage 0, row 35
        p[576 + 560 + lane] = z;      // stage 1, row 35
    }

    // B fragments (folded Wn as tf32), register-resident for the whole kernel.
    unsigned bfr[2][8][2];
#pragma unroll
    for (int nt = 0; nt < 2; nt++)
#pragma unroll
        for (int kt = 0; kt < 8; kt++) {
            bfr[nt][kt][0] = f2tf(WnP_g[(kt * 8 + t) * 16 + nt * 8 + q]);
            bfr[nt][kt][1] = f2tf(WnP_g[(kt * 8 + t + 4) * 16 + nt * 8 + q]);
        }

    // attn2 weights for this lane's 4 h's: {2t, 2t+1, 8+2t, 8+2t+1}
    const float2 a2lo = __ldg((const float2*)(a2w + 2 * t));
    const float2 a2hi = __ldg((const float2*)(a2w + 8 + 2 * t));
    const float  b2   = __ldg(a2b);

    __syncwarp();

    // ---- prologue: prefetch first tile into stage 0
    {
        const float4* src4 = (const float4*)xn + (size_t)(blockIdx.x * 4 + wid) * 560;
#pragma unroll
        for (int k = 0; k < 18; k++) {
            int idx = k * 32 + lane;
            if (idx < 560) {
                int row = idx >> 4, c4 = idx & 15;
                cp16(x_smem + (unsigned)(row * 16 + (c4 ^ (row & 7))) * 16, src4 + idx);
            }
        }
        cp_commit();
    }

    int st = 0;
    for (int g = blockIdx.x; g < 16384; g += GRID) {
        const int b = g * 4 + wid;

        // ---- prefetch next tile into other stage
        {
            int gn = g + GRID;
            if (gn < 16384) {
                const float4* src4 = (const float4*)xn + (size_t)(gn * 4 + wid) * 560;
                unsigned dst = x_smem + (unsigned)(st ^ 1) * 9216;
#pragma unroll
                for (int k = 0; k < 18; k++) {
                    int idx = k * 32 + lane;
                    if (idx < 560) {
                        int row = idx >> 4, c4 = idx & 15;
                        cp16(dst + (unsigned)(row * 16 + (c4 ^ (row & 7))) * 16, src4 + idx);
                    }
                }
            }
            cp_commit();
        }

        // ---- eb for current tile (hoisted; consumed after mma)
        const float2 eb0 = __ldg((const float2*)(eb_g + (size_t)b * 16 + 2 * t));
        const float2 eb1 = __ldg((const float2*)(eb_g + (size_t)b * 16 + 8 + 2 * t));

        // ---- wait for current tile
        cp_wait1();
        __syncwarp();

        const float*  xw  = (const float*)(xbase_c + st * 9216);
        const float4* xw4 = (const float4*)xw;

        // ---- phase 2: u[rows x 16] = x @ Wn via tf32 mma
        float cfr[3][2][4];
#pragma unroll
        for (int mt = 0; mt < 3; mt++)
#pragma unroll
            for (int nt = 0; nt < 2; nt++)
#pragma unroll
                for (int k = 0; k < 4; k++) cfr[mt][nt][k] = 0.f;

#pragma unroll
        for (int mt = 0; mt < 2; mt++) {
            const float* xr = xw + (mt * 16 + q) * 64 + t;   // (r&7)==q
#pragma unroll
            for (int kt = 0; kt < 8; kt++) {
                int o0 = ((2 * kt) ^ q) * 4;    // swizzled chunk for cols kt*8+t
                int o2 = o0 ^ 4;                 // cols kt*8+t+4
                unsigned a0 = f2tf(xr[o0]), a1 = f2tf(xr[o0 + 512]);
                unsigned a2 = f2tf(xr[o2]), a3 = f2tf(xr[o2 + 512]);
                mma_tf32(cfr[mt][0], a0, a1, a2, a3, bfr[0][kt][0], bfr[0][kt][1]);
                mma_tf32(cfr[mt][1], a0, a1, a2, a3, bfr[1][kt][0], bfr[1][kt][1]);
            }
        }
        // mt = 2: lo-half rows 32..34 (q<3), else clamp to zero row 35;
        //         hi-half rows 40..47 are out of range -> constant-0 A regs.
        {
            const int rq = (q < 3) ? (32 + q) : 35;   // row 35 = zeros, addr-safe
            const float* xr = xw + rq * 64 + t;
#pragma unroll
            for (int kt = 0; kt < 8; kt++) {
                int o0 = ((2 * kt) ^ q) * 4;
                int o2 = o0 ^ 4;
                unsigned a0 = f2tf(xr[o0]);
                unsigned a2 = f2tf(xr[o2]);
                mma_tf32(cfr[2][0], a0, 0u, a2, 0u, bfr[0][kt][0], bfr[0][kt][1]);
                mma_tf32(cfr[2][1], a0, 0u, a2, 0u, bfr[1][kt][0], bfr[1][kt][1]);
            }
        }

        // ---- phase 3: e per row from fragments, softmax over n (rows 0..34)
        float e[6];
#pragma unroll
        for (int mt = 0; mt < 3; mt++) {
            float plo, phi;
            plo =      a2lo.x * fmaxf(cfr[mt][0][0] + eb0.x, 0.f);
            plo = fmaf(a2lo.y,  fmaxf(cfr[mt][0][1] + eb0.y, 0.f), plo);
            plo = fmaf(a2hi.x,  fmaxf(cfr[mt][1][0] + eb1.x, 0.f), plo);
            plo = fmaf(a2hi.y,  fmaxf(cfr[mt][1][1] + eb1.y, 0.f), plo);
            phi =      a2lo.x * fmaxf(cfr[mt][0][2] + eb0.x, 0.f);
            phi = fmaf(a2lo.y,  fmaxf(cfr[mt][0][3] + eb0.y, 0.f), phi);
            phi = fmaf(a2hi.x,  fmaxf(cfr[mt][1][2] + eb1.x, 0.f), phi);
            phi = fmaf(a2hi.y,  fmaxf(cfr[mt][1][3] + eb1.y, 0.f), phi);
            plo += __shfl_xor_sync(0xffffffffu, plo, 1);
            plo += __shfl_xor_sync(0xffffffffu, plo, 2);
            phi += __shfl_xor_sync(0xffffffffu, phi, 1);
            phi += __shfl_xor_sync(0xffffffffu, phi, 2);
            float elo = plo + b2; elo = (elo > 0.f) ? elo : 0.2f * elo;
            float ehi = phi + b2; ehi = (ehi > 0.f) ? ehi : 0.2f * ehi;
            int rlo = mt * 16 + q;
            e[2 * mt]     = (rlo < 35)     ? elo : -INFINITY;
            e[2 * mt + 1] = (rlo + 8 < 35) ? ehi : -INFINITY;
        }

        // warp softmax: reduce across q (xor 4,8,16) — each row counted once
        float mx = e[0];
#pragma unroll
        for (int j = 1; j < 6; j++) mx = fmaxf(mx, e[j]);
        mx = fmaxf(mx, __shfl_xor_sync(0xffffffffu, mx, 4));
        mx = fmaxf(mx, __shfl_xor_sync(0xffffffffu, mx, 8));
        mx = fmaxf(mx, __shfl_xor_sync(0xffffffffu, mx, 16));

        float ax[6]; float sum = 0.f;
#pragma unroll
        for (int j = 0; j < 6; j++) { ax[j] = __expf(e[j] - mx); sum += ax[j]; }
        sum += __shfl_xor_sync(0xffffffffu, sum, 4);
        sum += __shfl_xor_sync(0xffffffffu, sum, 8);
        sum += __shfl_xor_sync(0xffffffffu, sum, 16);
        const float rinv = 1.0f / sum;

        if (t == 0) {
#pragma unroll
            for (int mt = 0; mt < 3; mt++) {
                int rlo = mt * 16 + q, rhi = rlo + 8;
                if (rlo < 35) a_s[rlo] = ax[2 * mt] * rinv;
                else if (rlo == 35) a_s[35] = 0.f;
                if (rhi < 35) a_s[rhi] = ax[2 * mt + 1] * rinv;
            }
        }
        __syncwarp();

        // ---- phase 4: s[c] = sum_n a_n x_n[c]; fp32 tile; lane=(cq,rh)
        float2 ap[9];
#pragma unroll
        for (int i = 0; i < 9; i++) ap[i] = *(const float2*)&a_s[rh * 18 + 2 * i];

        float4 acc = make_float4(0.f, 0.f, 0.f, 0.f);
#pragma unroll
        for (int p = 0; p < 18; p++) {
            int row = rh * 18 + p;                 // row 35 contributes 0 (a=0, x=0)
            float a = (p & 1) ? ap[p >> 1].y : ap[p >> 1].x;
            float4 xv = xw4[row * 16 + (cq ^ (row & 7))];
            acc.x = fmaf(a, xv.x, acc.x);
            acc.y = fmaf(a, xv.y, acc.y);
            acc.z = fmaf(a, xv.z, acc.z);
            acc.w = fmaf(a, xv.w, acc.w);
        }
        acc.x += __shfl_xor_sync(0xffffffffu, acc.x, 16);
        acc.y += __shfl_xor_sync(0xffffffffu, acc.y, 16);
        acc.z += __shfl_xor_sync(0xffffffffu, acc.z, 16);
        acc.w += __shfl_xor_sync(0xffffffffu, acc.w, 16);
        if (rh == 0)
            *((float4*)(s_g + (size_t)b * 64) + cq) = acc;
        __syncwarp();   // all lanes done with stage st before it is overwritten

        st ^= 1;
    }
}

// ---------------- K4: out = elu(align_w @ s + align_b) ----------------
// 128-batch tile per block, 256 threads, thread = 8b x 4d micro-tile.
#define OPITCH 68
__global__ __launch_bounds__(256)
void out_kernel(const float* __restrict__ aw,
                const float* __restrict__ abv,
                float* __restrict__ out) {
    __shared__ __align__(16) float s_s[128 * OPITCH];   // 34816 B
    __shared__ __align__(16) float w_t[64 * OPITCH];    // 17408 B
    __shared__ float ab_s[64];

    const int tid = threadIdx.x;
    const int b0  = blockIdx.x * 128;

    // W^T: w_t[c][d] = aw[d*64+c]
#pragma unroll
    for (int k = 0; k < 16; k++) {
        int idx = k * 256 + tid;
        int d = idx >> 6, c = idx & 63;
        w_t[c * OPITCH + d] = aw[idx];
    }
    if (tid < 64) ab_s[tid] = abv[tid];

    // stage s tile (128 rows), coalesced float4
#pragma unroll
    for (int k = 0; k < 8; k++) {
        int idx4 = k * 256 + tid;
        int bl = idx4 >> 4, c4 = idx4 & 15;
        *(float4*)&s_s[bl * OPITCH + c4 * 4] =
            ((const float4*)(s_g + (size_t)(b0 + bl) * 64))[c4];
    }
    __syncthreads();

    const int tx = tid & 15;     // d-group: d = 4*tx .. 4*tx+3
    const int ty = tid >> 4;     // b-group: b = 8*ty .. 8*ty+7

    ull acc2[8][2];
#pragma unroll
    for (int bi = 0; bi < 8; bi++) { acc2[bi][0] = 0ull; acc2[bi][1] = 0ull; }

#pragma unroll
    for (int cs = 0; cs < 16; cs++) {
        ulonglong2 wv[4];
#pragma unroll
        for (int j = 0; j < 4; j++)
            wv[j] = *(const ulonglong2*)&w_t[(4 * cs + j) * OPITCH + 4 * tx];
#pragma unroll
        for (int bi = 0; bi < 8; bi++) {
            float4 sv = *(const float4*)&s_s[(8 * ty + bi) * OPITCH + 4 * cs];
            ull a0 = splat2(sv.x), a1 = splat2(sv.y);
            ull a2 = splat2(sv.z), a3 = splat2(sv.w);
            fma2(acc2[bi][0], a0, wv[0].x); fma2(acc2[bi][1], a0, wv[0].y);
            fma2(acc2[bi][0], a1, wv[1].x); fma2(acc2[bi][1], a1, wv[1].y);
            fma2(acc2[bi][0], a2, wv[2].x); fma2(acc2[bi][1], a2, wv[2].y);
            fma2(acc2[bi][0], a3, wv[3].x); fma2(acc2[bi][1], a3, wv[3].y);
        }
    }

    float4 abv4 = *(const float4*)&ab_s[4 * tx];
#pragma unroll
    for (int bi = 0; bi < 8; bi++) {
        float2 lo = unpack2(acc2[bi][0]), hi = unpack2(acc2[bi][1]);
        float4 o;
        o.x = lo.x + abv4.x; o.x = (o.x > 0.f) ? o.x : expm1f(o.x);
        o.y = lo.y + abv4.y; o.y = (o.y > 0.f) ? o.y : expm1f(o.y);
        o.z = hi.x + abv4.z; o.z = (o.z > 0.f) ? o.z : expm1f(o.z);
        o.w = hi.y + abv4.w; o.w = (o.w > 0.f) ? o.w : expm1f(o.w);
        *(float4*)&out[(size_t)(b0 + 8 * ty + bi) * 64 + 4 * tx] = o;
    }
}

extern "C" void kernel_launch(void* const* d_in, const int* in_sizes, int n_in,
                              void* d_out, int out_size) {
    const float* x_target = (const float*)d_in[0];
    const float* x_neigh  = (const float*)d_in[1];
    const float* align_w  = (const float*)d_in[2];
    const float* align_b  = (const float*)d_in[3];
    const float* attn1_w  = (const float*)d_in[4];
    const float* attn1_b  = (const float*)d_in[5];
    const float* attn2_w  = (const float*)d_in[6];
    const float* attn2_b  = (const float*)d_in[7];
    float* out = (float*)d_out;

    static bool attr_set = false;
    if (!attr_set) {
        cudaFuncSetAttribute(gat_kernel, cudaFuncAttributeMaxDynamicSharedMemorySize, 74304);
        attr_set = true;
    }

    prep_kernel<<<9, 128>>>(align_w, align_b, attn1_w, attn1_b);
    eb_kernel<<<2048, 128>>>(x_target);
    gat_kernel<<<GRID, 128, 74304>>>(x_neigh, attn2_w, attn2_b);
    out_kernel<<<512, 256>>>(align_w, align_b, out);
}